// round 14
// baseline (speedup 1.0000x reference)
#include <cuda_runtime.h>
#include <cuda_fp16.h>
#include <cstdint>

#define THREADS 256
#define M_TILE  128

// ---------------- SMEM layout (bytes), MMA buffers 1024-aligned ----------------
#define OFF_B1   0
#define OFF_B2   256
#define OFF_X0   1024                  // 128 x 64 fp16 (128B rows, SW128) = 16384
#define OFF_X1   (OFF_X0 + 16384)      // 17408  (double buffer)
#define OFF_W1   (OFF_X1 + 16384)      // 33792  (192 x 64 fp16) = 24576
#define OFF_W2   (OFF_W1 + 24576)      // 58368  (64 x 64 fp16)  = 8192
#define SMEM_BYTES (OFF_W2 + 8192)     // 66560 -> 3 CTAs/SM

// ---------------- helpers ----------------
__device__ __forceinline__ uint32_t smem_u32(const void* p) {
    uint32_t a;
    asm("{ .reg .u64 t; cvta.to.shared.u64 t, %1; cvt.u32.u64 %0, t; }" : "=r"(a) : "l"(p));
    return a;
}
__device__ __forceinline__ uint32_t sw128(uint32_t o) { return o ^ ((o >> 3) & 0x70); }

__device__ __forceinline__ uint32_t f2h2(float a, float b) {
    __half2 h = __floats2half2_rn(a, b);
    return *(uint32_t*)&h;
}

__device__ __forceinline__ void ldsm4(uint32_t r[4], uint32_t addr) {
    asm volatile("ldmatrix.sync.aligned.m8n8.x4.shared.b16 {%0,%1,%2,%3}, [%4];"
        : "=r"(r[0]), "=r"(r[1]), "=r"(r[2]), "=r"(r[3]) : "r"(addr));
}
__device__ __forceinline__ void ldsm4t(uint32_t r[4], uint32_t addr) {
    asm volatile("ldmatrix.sync.aligned.m8n8.x4.trans.shared.b16 {%0,%1,%2,%3}, [%4];"
        : "=r"(r[0]), "=r"(r[1]), "=r"(r[2]), "=r"(r[3]) : "r"(addr));
}
__device__ __forceinline__ void mma16816(float c[4], const uint32_t a[4], const uint32_t b[2]) {
    asm volatile(
        "mma.sync.aligned.m16n8k16.row.col.f32.f16.f16.f32 "
        "{%0,%1,%2,%3}, {%4,%5,%6,%7}, {%8,%9}, {%0,%1,%2,%3};"
        : "+f"(c[0]), "+f"(c[1]), "+f"(c[2]), "+f"(c[3])
        : "r"(a[0]), "r"(a[1]), "r"(a[2]), "r"(a[3]), "r"(b[0]), "r"(b[1]));
}
__device__ __forceinline__ uint32_t frag_addr(uint32_t base, int rbase, int cbase, int lane) {
    int row  = rbase + (lane & 15);
    int colb = cbase * 2 + (lane & 16);
    return base + sw128((uint32_t)(row * 128 + colb));
}

__global__ __launch_bounds__(THREADS, 3)
void edge_mlp_f16(const float* __restrict__ src, const float* __restrict__ dst,
                  const float* __restrict__ ea,
                  const float* __restrict__ W1, const float* __restrict__ b1,
                  const float* __restrict__ W2, const float* __restrict__ b2,
                  float* __restrict__ out, int E, int ntiles)
{
    extern __shared__ char smem[];
    const uint32_t sb = smem_u32(smem);
    const int tid = threadIdx.x;
    const int lid = tid & 31;
    const int wid = tid >> 5;

    const int wm = wid & 3;   // M group: rows 32*wm .. +31
    const int wn = wid >> 2;  // N group: cols 32*wn .. +31

    // ================= ONE-TIME: biases + fp16 weights =================
    if (tid < 64) {
        ((float*)(smem + OFF_B1))[tid] = b1[tid];
        ((float*)(smem + OFF_B2))[tid] = b2[tid];
    }
    #pragma unroll
    for (int i = 0; i < 12; ++i) {
        int idx = tid + i * THREADS;               // float4 index, 0..3071
        float4 v = ((const float4*)W1)[idx];
        uint32_t off = sw128((uint32_t)((idx >> 4) * 128 + (idx & 15) * 8));
        *(uint2*)(smem + OFF_W1 + off) = make_uint2(f2h2(v.x, v.y), f2h2(v.z, v.w));
    }
    #pragma unroll
    for (int i = 0; i < 4; ++i) {
        int idx = tid + i * THREADS;               // 0..1023
        float4 v = ((const float4*)W2)[idx];
        uint32_t off = sw128((uint32_t)((idx >> 4) * 128 + (idx & 15) * 8));
        *(uint2*)(smem + OFF_W2 + off) = make_uint2(f2h2(v.x, v.y), f2h2(v.z, v.w));
    }

    float acc[2][4][4];
    #pragma unroll
    for (int mt = 0; mt < 2; ++mt)
        #pragma unroll
        for (int nt = 0; nt < 4; ++nt)
            #pragma unroll
            for (int j = 0; j < 4; ++j) acc[mt][nt][j] = 0.f;

    // ---- LDG batch of 4 float4s for half a segment ----
    auto ldg4 = [&](const float* __restrict__ p, int e0, int g, float4* v) {
        #pragma unroll
        for (int i = 0; i < 4; ++i) {
            int idx = tid + (g * 4 + i) * THREADS;   // 0..2047
            int e = e0 + (idx >> 4);
            v[i] = (e < E) ? ((const float4*)p)[(size_t)e * 16 + (idx & 15)]
                           : make_float4(0.f, 0.f, 0.f, 0.f);
        }
    };
    // ---- convert + store a batch into X buffer xb ----
    auto sts4 = [&](uint32_t xoff, int g, const float4* v) {
        #pragma unroll
        for (int i = 0; i < 4; ++i) {
            int idx = tid + (g * 4 + i) * THREADS;
            uint32_t off = sw128((uint32_t)((idx >> 4) * 128 + (idx & 15) * 8));
            *(uint2*)(smem + xoff + off) =
                make_uint2(f2h2(v[i].x, v[i].y), f2h2(v[i].z, v[i].w));
        }
    };

    // one 16-wide k-step, 1 term: acc += x*w  (A from buffer xb)
    auto kstep = [&](uint32_t xb, int kk, uint32_t wb, int kg) {
        uint32_t bf[2][4], af[2][4];
        ldsm4t(bf[0], frag_addr(wb, kg, wn * 32,      lid));
        ldsm4t(bf[1], frag_addr(wb, kg, wn * 32 + 16, lid));
        ldsm4(af[0], frag_addr(xb, wm * 32,      kk, lid));
        ldsm4(af[1], frag_addr(xb, wm * 32 + 16, kk, lid));
        #pragma unroll
        for (int mt = 0; mt < 2; ++mt)
            #pragma unroll
            for (int nt = 0; nt < 4; ++nt)
                mma16816(acc[mt][nt], af[mt], &bf[nt >> 1][(nt & 1) * 2]);
    };

    // pipelined phase: mma current buffer (W1 rows kgb..kgb+63) while
    // loading/storing next segment into the other buffer
    auto phase = [&](uint32_t xcur, uint32_t xnxt, int kgb,
                     const float* __restrict__ ldp, int lde0, bool doload) {
        float4 v[4];
        if (doload) ldg4(ldp, lde0, 0, v);
        kstep(sb + xcur, 0,  sb + OFF_W1, kgb);
        kstep(sb + xcur, 16, sb + OFF_W1, kgb + 16);
        if (doload) sts4(xnxt, 0, v);
        if (doload) ldg4(ldp, lde0, 1, v);
        kstep(sb + xcur, 32, sb + OFF_W1, kgb + 32);
        kstep(sb + xcur, 48, sb + OFF_W1, kgb + 48);
        if (doload) sts4(xnxt, 1, v);
        __syncthreads();
    };

    // ================= prologue: stage first tile's src =================
    int t0 = blockIdx.x;
    uint32_t xcur = OFF_X0, xnxt = OFF_X1;
    if (t0 < ntiles) {
        float4 v[4];
        ldg4(src, t0 * M_TILE, 0, v); sts4(xcur, 0, v);
        ldg4(src, t0 * M_TILE, 1, v); sts4(xcur, 1, v);
    }
    __syncthreads();

    // ================= persistent tile loop =================
    for (int t = t0; t < ntiles; t += gridDim.x) {
        const int e0 = t * M_TILE;
        const int tn = t + gridDim.x;
        const bool more = (tn < ntiles);

        // P1: mma src (W1 0..63)    | load dst
        phase(xcur, xnxt, 0,   dst, e0, true);
        { uint32_t tmp = xcur; xcur = xnxt; xnxt = tmp; }
        // P2: mma dst (W1 64..127)  | load ea
        phase(xcur, xnxt, 64,  ea,  e0, true);
        { uint32_t tmp = xcur; xcur = xnxt; xnxt = tmp; }
        // P3: mma ea  (W1 128..191) | load next tile's src
        phase(xcur, xnxt, 128, src, tn * M_TILE, more);
        { uint32_t tmp = xcur; xcur = xnxt; xnxt = tmp; }
        // now: xcur = next tile's src, xnxt = dead (ea) buffer -> H target

        // ---- bias1 + ReLU -> fp16 H plane in xnxt ----
        {
            const float* b1s = (const float*)(smem + OFF_B1);
            #pragma unroll
            for (int mt = 0; mt < 2; ++mt)
                #pragma unroll
                for (int nt = 0; nt < 4; ++nt) {
                    int row = wm * 32 + mt * 16 + (lid >> 2);
                    int col = wn * 32 + nt * 8 + (lid & 3) * 2;
                    float bc0 = b1s[col], bc1 = b1s[col + 1];
                    float h0 = fmaxf(acc[mt][nt][0] + bc0, 0.f);
                    float h1 = fmaxf(acc[mt][nt][1] + bc1, 0.f);
                    float h2 = fmaxf(acc[mt][nt][2] + bc0, 0.f);
                    float h3 = fmaxf(acc[mt][nt][3] + bc1, 0.f);
                    uint32_t oA = sw128((uint32_t)(row * 128 + col * 2));
                    uint32_t oB = sw128((uint32_t)((row + 8) * 128 + col * 2));
                    *(uint32_t*)(smem + xnxt + oA) = f2h2(h0, h1);
                    *(uint32_t*)(smem + xnxt + oB) = f2h2(h2, h3);
                    acc[mt][nt][0] = acc[mt][nt][1] = acc[mt][nt][2] = acc[mt][nt][3] = 0.f;
                }
        }
        __syncthreads();

        // ---- GEMM2 (K = 64) from H in xnxt ----
        #pragma unroll
        for (int ks = 0; ks < 4; ++ks)
            kstep(sb + xnxt, ks * 16, sb + OFF_W2, ks * 16);

        // ---- epilogue: + bias2, float2 stores; reset acc ----
        {
            const float* b2s = (const float*)(smem + OFF_B2);
            #pragma unroll
            for (int mt = 0; mt < 2; ++mt)
                #pragma unroll
                for (int nt = 0; nt < 4; ++nt) {
                    int row = wm * 32 + mt * 16 + (lid >> 2);
                    int col = wn * 32 + nt * 8 + (lid & 3) * 2;
                    float bc0 = b2s[col], bc1 = b2s[col + 1];
                    int eA = e0 + row, eB = e0 + row + 8;
                    if (eA < E)
                        *(float2*)&out[(size_t)eA * 64 + col] =
                            make_float2(acc[mt][nt][0] + bc0, acc[mt][nt][1] + bc1);
                    if (eB < E)
                        *(float2*)&out[(size_t)eB * 64 + col] =
                            make_float2(acc[mt][nt][2] + bc0, acc[mt][nt][3] + bc1);
                    acc[mt][nt][0] = acc[mt][nt][1] = acc[mt][nt][2] = acc[mt][nt][3] = 0.f;
                }
        }
        __syncthreads();   // GEMM2 reads of xnxt done before next tile's P1 sts
    }
}

extern "C" void kernel_launch(void* const* d_in, const int* in_sizes, int n_in,
                              void* d_out, int out_size)
{
    const float* src = (const float*)d_in[0];
    const float* dst = (const float*)d_in[1];
    const float* ea  = (const float*)d_in[2];
    const float* W1  = (const float*)d_in[5];
    const float* b1  = (const float*)d_in[6];
    const float* W2  = (const float*)d_in[7];
    const float* b2  = (const float*)d_in[8];
    float* out = (float*)d_out;

    int E = in_sizes[0] / 64;
    int ntiles = (E + M_TILE - 1) / M_TILE;

    cudaFuncSetAttribute(edge_mlp_f16,
                         cudaFuncAttributeMaxDynamicSharedMemorySize, SMEM_BYTES);

    int grid = 3 * 148;
    if (grid > ntiles) grid = ntiles;
    edge_mlp_f16<<<grid, THREADS, SMEM_BYTES>>>(src, dst, ea, W1, b1, W2, b2, out, E, ntiles);
}

// round 15
// speedup vs baseline: 1.4075x; 1.4075x over previous
#include <cuda_runtime.h>
#include <cuda_fp16.h>
#include <cstdint>

#define THREADS 256
#define M_TILE  128

// ---------------- SMEM layout (bytes) ----------------
#define OFF_B1   0
#define OFF_B2   256
#define OFF_X0   1024                  // 128 x 64 fp32 (256B rows, 32B-unit swizzle) = 32768
#define OFF_X1   (OFF_X0 + 32768)      // 33792 (double buffer)
#define OFF_W1   (OFF_X1 + 32768)      // 66560 (192 x 64 fp16, 128B rows, SW128) = 24576
#define OFF_W2   (OFF_W1 + 24576)      // 91136 (64 x 64 fp16) = 8192
#define SMEM_BYTES (OFF_W2 + 8192)     // 99328 -> 2 CTAs/SM

// ---------------- helpers ----------------
__device__ __forceinline__ uint32_t smem_u32(const void* p) {
    uint32_t a;
    asm("{ .reg .u64 t; cvta.to.shared.u64 t, %1; cvt.u32.u64 %0, t; }" : "=r"(a) : "l"(p));
    return a;
}
__device__ __forceinline__ uint32_t sw128(uint32_t o) { return o ^ ((o >> 3) & 0x70); }
// fp32 X buffer swizzle: XOR 32B-unit index (bits [5:7]) with row bits [8:10]
__device__ __forceinline__ uint32_t swx(uint32_t o)   { return o ^ ((o >> 3) & 0xE0); }

__device__ __forceinline__ uint32_t f2h2(float a, float b) {
    __half2 h = __floats2half2_rn(a, b);
    return *(uint32_t*)&h;
}

__device__ __forceinline__ void ldsm4(uint32_t r[4], uint32_t addr) {
    asm volatile("ldmatrix.sync.aligned.m8n8.x4.shared.b16 {%0,%1,%2,%3}, [%4];"
        : "=r"(r[0]), "=r"(r[1]), "=r"(r[2]), "=r"(r[3]) : "r"(addr));
}
__device__ __forceinline__ void ldsm4t(uint32_t r[4], uint32_t addr) {
    asm volatile("ldmatrix.sync.aligned.m8n8.x4.trans.shared.b16 {%0,%1,%2,%3}, [%4];"
        : "=r"(r[0]), "=r"(r[1]), "=r"(r[2]), "=r"(r[3]) : "r"(addr));
}
__device__ __forceinline__ void mma16816(float c[4], const uint32_t a[4], const uint32_t b[2]) {
    asm volatile(
        "mma.sync.aligned.m16n8k16.row.col.f32.f16.f16.f32 "
        "{%0,%1,%2,%3}, {%4,%5,%6,%7}, {%8,%9}, {%0,%1,%2,%3};"
        : "+f"(c[0]), "+f"(c[1]), "+f"(c[2]), "+f"(c[3])
        : "r"(a[0]), "r"(a[1]), "r"(a[2]), "r"(a[3]), "r"(b[0]), "r"(b[1]));
}
__device__ __forceinline__ uint32_t frag_addr(uint32_t base, int rbase, int cbase, int lane) {
    int row  = rbase + (lane & 15);
    int colb = cbase * 2 + (lane & 16);
    return base + sw128((uint32_t)(row * 128 + colb));
}
__device__ __forceinline__ void cpasync16(uint32_t smem, const void* g, int bytes) {
    asm volatile("cp.async.cg.shared.global [%0], [%1], 16, %2;"
                 :: "r"(smem), "l"(g), "r"(bytes) : "memory");
}
#define CP_COMMIT() asm volatile("cp.async.commit_group;" ::: "memory")
#define CP_WAIT0()  asm volatile("cp.async.wait_group 0;" ::: "memory")

__global__ __launch_bounds__(THREADS, 2)
void edge_mlp_f16(const float* __restrict__ src, const float* __restrict__ dst,
                  const float* __restrict__ ea,
                  const float* __restrict__ W1, const float* __restrict__ b1,
                  const float* __restrict__ W2, const float* __restrict__ b2,
                  float* __restrict__ out, int E, int ntiles)
{
    extern __shared__ char smem[];
    const uint32_t sb = smem_u32(smem);
    const int tid = threadIdx.x;
    const int lid = tid & 31;
    const int wid = tid >> 5;

    const int wm = wid & 3;   // M group: rows 32*wm .. +31
    const int wn = wid >> 2;  // N group: cols 32*wn .. +31

    // ================= ONE-TIME: biases + fp16 weights =================
    if (tid < 64) {
        ((float*)(smem + OFF_B1))[tid] = b1[tid];
        ((float*)(smem + OFF_B2))[tid] = b2[tid];
    }
    #pragma unroll
    for (int i = 0; i < 12; ++i) {
        int idx = tid + i * THREADS;               // float4 index, 0..3071
        float4 v = ((const float4*)W1)[idx];
        uint32_t off = sw128((uint32_t)((idx >> 4) * 128 + (idx & 15) * 8));
        *(uint2*)(smem + OFF_W1 + off) = make_uint2(f2h2(v.x, v.y), f2h2(v.z, v.w));
    }
    #pragma unroll
    for (int i = 0; i < 4; ++i) {
        int idx = tid + i * THREADS;               // 0..1023
        float4 v = ((const float4*)W2)[idx];
        uint32_t off = sw128((uint32_t)((idx >> 4) * 128 + (idx & 15) * 8));
        *(uint2*)(smem + OFF_W2 + off) = make_uint2(f2h2(v.x, v.y), f2h2(v.z, v.w));
    }

    float acc[2][4][4];
    #pragma unroll
    for (int mt = 0; mt < 2; ++mt)
        #pragma unroll
        for (int nt = 0; nt < 4; ++nt)
            #pragma unroll
            for (int j = 0; j < 4; ++j) acc[mt][nt][j] = 0.f;

    // ---- async stage: 2048 16B chunks (128 rows x 16), raw fp32, swizzled ----
    auto stage_async = [&](const float* __restrict__ p, int e0, uint32_t xoff) {
        #pragma unroll
        for (int i = 0; i < 8; ++i) {
            int idx = tid + i * THREADS;           // 0..2047
            int row = idx >> 4;
            int ch  = idx & 15;
            int e   = e0 + row;
            int ec  = (e < E) ? e : (E - 1);
            uint32_t so = swx((uint32_t)(row * 256 + ch * 16));
            cpasync16(sb + xoff + so,
                      (const char*)p + ((size_t)ec * 256 + (size_t)ch * 16),
                      (e < E) ? 16 : 0);
        }
        CP_COMMIT();
    };

    // ---- fp32 LDS.64 with X swizzle ----
    auto lds64 = [&](uint32_t xoff, int r, int c) -> float2 {
        uint32_t so = swx((uint32_t)(r * 256 + c * 4));
        return *(const float2*)(smem + xoff + so);
    };

    // GEMM1 k-step: A built from fp32 X via LDS+cvt, B from W1 via ldsm
    auto kstep32 = [&](uint32_t xoff, int kk, int kg) {
        uint32_t bf[2][4], af[2][4];
        ldsm4t(bf[0], frag_addr(sb + OFF_W1, kg, wn * 32,      lid));
        ldsm4t(bf[1], frag_addr(sb + OFF_W1, kg, wn * 32 + 16, lid));
        #pragma unroll
        for (int mt = 0; mt < 2; ++mt) {
            int r0 = wm * 32 + mt * 16 + (lid >> 2);
            int c0 = kk + (lid & 3) * 2;
            float2 f0 = lds64(xoff, r0,     c0);
            float2 f1 = lds64(xoff, r0 + 8, c0);
            float2 f2 = lds64(xoff, r0,     c0 + 8);
            float2 f3 = lds64(xoff, r0 + 8, c0 + 8);
            af[mt][0] = f2h2(f0.x, f0.y);
            af[mt][1] = f2h2(f1.x, f1.y);
            af[mt][2] = f2h2(f2.x, f2.y);
            af[mt][3] = f2h2(f3.x, f3.y);
        }
        #pragma unroll
        for (int mt = 0; mt < 2; ++mt)
            #pragma unroll
            for (int nt = 0; nt < 4; ++nt)
                mma16816(acc[mt][nt], af[mt], &bf[nt >> 1][(nt & 1) * 2]);
    };

    // GEMM2 k-step: A from fp16 H plane (ldsm), B from W2
    auto kstep16 = [&](uint32_t xoff, int kk, int kg) {
        uint32_t bf[2][4], af[2][4];
        ldsm4t(bf[0], frag_addr(sb + OFF_W2, kg, wn * 32,      lid));
        ldsm4t(bf[1], frag_addr(sb + OFF_W2, kg, wn * 32 + 16, lid));
        ldsm4(af[0], frag_addr(sb + xoff, wm * 32,      kk, lid));
        ldsm4(af[1], frag_addr(sb + xoff, wm * 32 + 16, kk, lid));
        #pragma unroll
        for (int mt = 0; mt < 2; ++mt)
            #pragma unroll
            for (int nt = 0; nt < 4; ++nt)
                mma16816(acc[mt][nt], af[mt], &bf[nt >> 1][(nt & 1) * 2]);
    };

    // ================= prologue: async-stage first tile's src =================
    int t0 = blockIdx.x;
    uint32_t xcur = OFF_X0, xnxt = OFF_X1;
    if (t0 < ntiles) stage_async(src, t0 * M_TILE, xcur);
    CP_WAIT0();
    __syncthreads();

    // ================= persistent tile loop =================
    for (int t = t0; t < ntiles; t += gridDim.x) {
        const int e0 = t * M_TILE;
        const int tn = t + gridDim.x;
        const bool more = (tn < ntiles);

        // P1: copy dst -> xnxt (async) | mma src (W1 rows 0..63)
        stage_async(dst, e0, xnxt);
        #pragma unroll
        for (int ks = 0; ks < 4; ++ks) kstep32(xcur, ks * 16, ks * 16);
        CP_WAIT0();
        __syncthreads();
        { uint32_t tmp = xcur; xcur = xnxt; xnxt = tmp; }

        // P2: copy ea -> xnxt | mma dst (W1 rows 64..127)
        stage_async(ea, e0, xnxt);
        #pragma unroll
        for (int ks = 0; ks < 4; ++ks) kstep32(xcur, ks * 16, 64 + ks * 16);
        CP_WAIT0();
        __syncthreads();
        { uint32_t tmp = xcur; xcur = xnxt; xnxt = tmp; }

        // P3: copy next tile's src -> xnxt (wait deferred) | mma ea (W1 128..191)
        if (more) stage_async(src, tn * M_TILE, xnxt);
        #pragma unroll
        for (int ks = 0; ks < 4; ++ks) kstep32(xcur, ks * 16, 128 + ks * 16);
        __syncthreads();                           // all warps done reading ea buffer

        // ---- bias1 + ReLU -> fp16 H plane into xcur (dead ea buffer) ----
        {
            const float* b1s = (const float*)(smem + OFF_B1);
            #pragma unroll
            for (int mt = 0; mt < 2; ++mt)
                #pragma unroll
                for (int nt = 0; nt < 4; ++nt) {
                    int row = wm * 32 + mt * 16 + (lid >> 2);
                    int col = wn * 32 + nt * 8 + (lid & 3) * 2;
                    float bc0 = b1s[col], bc1 = b1s[col + 1];
                    float h0 = fmaxf(acc[mt][nt][0] + bc0, 0.f);
                    float h1 = fmaxf(acc[mt][nt][1] + bc1, 0.f);
                    float h2 = fmaxf(acc[mt][nt][2] + bc0, 0.f);
                    float h3 = fmaxf(acc[mt][nt][3] + bc1, 0.f);
                    uint32_t oA = sw128((uint32_t)(row * 128 + col * 2));
                    uint32_t oB = sw128((uint32_t)((row + 8) * 128 + col * 2));
                    *(uint32_t*)(smem + xcur + oA) = f2h2(h0, h1);
                    *(uint32_t*)(smem + xcur + oB) = f2h2(h2, h3);
                    acc[mt][nt][0] = acc[mt][nt][1] = acc[mt][nt][2] = acc[mt][nt][3] = 0.f;
                }
        }
        __syncthreads();

        // ---- GEMM2 (K = 64) from H ----
        #pragma unroll
        for (int ks = 0; ks < 4; ++ks) kstep16(xcur, ks * 16, ks * 16);

        // ---- epilogue: + bias2, float2 stores; reset acc ----
        {
            const float* b2s = (const float*)(smem + OFF_B2);
            #pragma unroll
            for (int mt = 0; mt < 2; ++mt)
                #pragma unroll
                for (int nt = 0; nt < 4; ++nt) {
                    int row = wm * 32 + mt * 16 + (lid >> 2);
                    int col = wn * 32 + nt * 8 + (lid & 3) * 2;
                    float bc0 = b2s[col], bc1 = b2s[col + 1];
                    int eA = e0 + row, eB = e0 + row + 8;
                    if (eA < E)
                        *(float2*)&out[(size_t)eA * 64 + col] =
                            make_float2(acc[mt][nt][0] + bc0, acc[mt][nt][1] + bc1);
                    if (eB < E)
                        *(float2*)&out[(size_t)eB * 64 + col] =
                            make_float2(acc[mt][nt][2] + bc0, acc[mt][nt][3] + bc1);
                    acc[mt][nt][0] = acc[mt][nt][1] = acc[mt][nt][2] = acc[mt][nt][3] = 0.f;
                }
        }
        CP_WAIT0();                                // next tile's src landed
        __syncthreads();                           // + H reads complete
        { uint32_t tmp = xcur; xcur = xnxt; xnxt = tmp; }   // xcur = next src
    }
}

extern "C" void kernel_launch(void* const* d_in, const int* in_sizes, int n_in,
                              void* d_out, int out_size)
{
    const float* src = (const float*)d_in[0];
    const float* dst = (const float*)d_in[1];
    const float* ea  = (const float*)d_in[2];
    const float* W1  = (const float*)d_in[5];
    const float* b1  = (const float*)d_in[6];
    const float* W2  = (const float*)d_in[7];
    const float* b2  = (const float*)d_in[8];
    float* out = (float*)d_out;

    int E = in_sizes[0] / 64;
    int ntiles = (E + M_TILE - 1) / M_TILE;

    cudaFuncSetAttribute(edge_mlp_f16,
                         cudaFuncAttributeMaxDynamicSharedMemorySize, SMEM_BYTES);

    int grid = 2 * 148;
    if (grid > ntiles) grid = ntiles;
    edge_mlp_f16<<<grid, THREADS, SMEM_BYTES>>>(src, dst, ea, W1, b1, W2, b2, out, E, ntiles);
}

// round 16
// speedup vs baseline: 1.4156x; 1.0057x over previous
#include <cuda_runtime.h>
#include <cuda_fp16.h>
#include <cstdint>

#define THREADS 256
#define M_TILE  256

// ---------------- SMEM layout (bytes), MMA buffers 1024-aligned ----------------
#define OFF_B1   0
#define OFF_B2   256
#define OFF_X    1024                  // 256 x 64 fp16 (128B rows, SW128) = 32768
#define OFF_W1   (OFF_X + 32768)       // 33792  (192 x 64 fp16) = 24576
#define OFF_W2   (OFF_W1 + 24576)      // 58368  (64 x 64 fp16)  = 8192
#define SMEM_BYTES (OFF_W2 + 8192)     // 66560 -> 2 CTAs/SM

// ---------------- helpers ----------------
__device__ __forceinline__ uint32_t smem_u32(const void* p) {
    uint32_t a;
    asm("{ .reg .u64 t; cvta.to.shared.u64 t, %1; cvt.u32.u64 %0, t; }" : "=r"(a) : "l"(p));
    return a;
}
__device__ __forceinline__ uint32_t sw128(uint32_t o) { return o ^ ((o >> 3) & 0x70); }

__device__ __forceinline__ uint32_t f2h2(float a, float b) {
    __half2 h = __floats2half2_rn(a, b);
    return *(uint32_t*)&h;
}

__device__ __forceinline__ void ldsm4(uint32_t r[4], uint32_t addr) {
    asm volatile("ldmatrix.sync.aligned.m8n8.x4.shared.b16 {%0,%1,%2,%3}, [%4];"
        : "=r"(r[0]), "=r"(r[1]), "=r"(r[2]), "=r"(r[3]) : "r"(addr));
}
__device__ __forceinline__ void ldsm4t(uint32_t r[4], uint32_t addr) {
    asm volatile("ldmatrix.sync.aligned.m8n8.x4.trans.shared.b16 {%0,%1,%2,%3}, [%4];"
        : "=r"(r[0]), "=r"(r[1]), "=r"(r[2]), "=r"(r[3]) : "r"(addr));
}
__device__ __forceinline__ void mma16816(float c[4], const uint32_t a[4], const uint32_t b[2]) {
    asm volatile(
        "mma.sync.aligned.m16n8k16.row.col.f32.f16.f16.f32 "
        "{%0,%1,%2,%3}, {%4,%5,%6,%7}, {%8,%9}, {%0,%1,%2,%3};"
        : "+f"(c[0]), "+f"(c[1]), "+f"(c[2]), "+f"(c[3])
        : "r"(a[0]), "r"(a[1]), "r"(a[2]), "r"(a[3]), "r"(b[0]), "r"(b[1]));
}
__device__ __forceinline__ uint32_t frag_addr(uint32_t base, int rbase, int cbase, int lane) {
    int row  = rbase + (lane & 15);
    int colb = cbase * 2 + (lane & 16);
    return base + sw128((uint32_t)(row * 128 + colb));
}
__device__ __forceinline__ void prefetch_l2(const void* p) {
    asm volatile("prefetch.global.L2 [%0];" :: "l"(p));
}

__global__ __launch_bounds__(THREADS, 2)
void edge_mlp_f16(const float* __restrict__ src, const float* __restrict__ dst,
                  const float* __restrict__ ea,
                  const float* __restrict__ W1, const float* __restrict__ b1,
                  const float* __restrict__ W2, const float* __restrict__ b2,
                  float* __restrict__ out, int E, int ntiles)
{
    extern __shared__ char smem[];
    const uint32_t sb = smem_u32(smem);
    const int tid = threadIdx.x;
    const int lid = tid & 31;
    const int wid = tid >> 5;

    const int wm = wid & 3;   // M group: rows 64*wm .. +63
    const int wn = wid >> 2;  // N group: cols 32*wn .. +31

    // ================= ONE-TIME: biases + fp16 weights =================
    if (tid < 64) {
        ((float*)(smem + OFF_B1))[tid] = b1[tid];
        ((float*)(smem + OFF_B2))[tid] = b2[tid];
    }
    #pragma unroll
    for (int i = 0; i < 12; ++i) {
        int idx = tid + i * THREADS;               // float4 index, 0..3071
        float4 v = ((const float4*)W1)[idx];
        uint32_t off = sw128((uint32_t)((idx >> 4) * 128 + (idx & 15) * 8));
        *(uint2*)(smem + OFF_W1 + off) = make_uint2(f2h2(v.x, v.y), f2h2(v.z, v.w));
    }
    #pragma unroll
    for (int i = 0; i < 4; ++i) {
        int idx = tid + i * THREADS;               // 0..1023
        float4 v = ((const float4*)W2)[idx];
        uint32_t off = sw128((uint32_t)((idx >> 4) * 128 + (idx & 15) * 8));
        *(uint2*)(smem + OFF_W2 + off) = make_uint2(f2h2(v.x, v.y), f2h2(v.z, v.w));
    }

    float acc[4][4][4];
    #pragma unroll
    for (int mt = 0; mt < 4; ++mt)
        #pragma unroll
        for (int nt = 0; nt < 4; ++nt)
            #pragma unroll
            for (int j = 0; j < 4; ++j) acc[mt][nt][j] = 0.f;

    // ---- X staging: 4 batches of 4 LDGs (4096 float4s total), fp16 plane ----
    auto stage_x = [&](const float* __restrict__ p, int e0, const float* __restrict__ pre) {
        #pragma unroll
        for (int g = 0; g < 4; ++g) {
            float4 v[4];
            #pragma unroll
            for (int i = 0; i < 4; ++i) {
                int idx = tid + (g * 4 + i) * THREADS;   // 0..4095
                int e = e0 + (idx >> 4);
                v[i] = (e < E) ? ((const float4*)p)[(size_t)e * 16 + (idx & 15)]
                               : make_float4(0.f, 0.f, 0.f, 0.f);
            }
            if (g == 0 && pre) {
                prefetch_l2((const char*)pre + (size_t)tid * 256);
                prefetch_l2((const char*)pre + (size_t)tid * 256 + 128);
            }
            #pragma unroll
            for (int i = 0; i < 4; ++i) {
                int idx = tid + (g * 4 + i) * THREADS;
                uint32_t off = sw128((uint32_t)((idx >> 4) * 128 + (idx & 15) * 8));
                *(uint2*)(smem + OFF_X + off) =
                    make_uint2(f2h2(v[i].x, v[i].y), f2h2(v[i].z, v[i].w));
            }
        }
    };

    // one 16-wide k-step: 4 A-frags (64 rows), 2 B-frags (32 cols), 16 mma
    auto kstep = [&](int kk, uint32_t wb, int kg) {
        uint32_t bf[2][4], af[4][4];
        ldsm4t(bf[0], frag_addr(wb, kg, wn * 32,      lid));
        ldsm4t(bf[1], frag_addr(wb, kg, wn * 32 + 16, lid));
        #pragma unroll
        for (int mt = 0; mt < 4; ++mt)
            ldsm4(af[mt], frag_addr(sb + OFF_X, wm * 64 + mt * 16, kk, lid));
        #pragma unroll
        for (int mt = 0; mt < 4; ++mt)
            #pragma unroll
            for (int nt = 0; nt < 4; ++nt)
                mma16816(acc[mt][nt], af[mt], &bf[nt >> 1][(nt & 1) * 2]);
    };

    // ================= persistent tile loop =================
    for (int t = blockIdx.x; t < ntiles; t += gridDim.x) {
        const int e0 = t * M_TILE;

        stage_x(src, e0, dst + (size_t)e0 * 64);
        __syncthreads();
        #pragma unroll
        for (int ks = 0; ks < 4; ++ks) kstep(ks * 16, sb + OFF_W1, ks * 16);
        __syncthreads();

        stage_x(dst, e0, ea + (size_t)e0 * 64);
        __syncthreads();
        #pragma unroll
        for (int ks = 0; ks < 4; ++ks) kstep(ks * 16, sb + OFF_W1, 64 + ks * 16);
        __syncthreads();

        {
            int tn = t + gridDim.x;
            const float* nxt = (tn < ntiles) ? src + (size_t)tn * M_TILE * 64
                                             : src + (size_t)e0 * 64;
            stage_x(ea, e0, nxt);
        }
        __syncthreads();
        #pragma unroll
        for (int ks = 0; ks < 4; ++ks) kstep(ks * 16, sb + OFF_W1, 128 + ks * 16);
        __syncthreads();                           // GEMM1 reads done; X free for H

        // ---- bias1 + ReLU -> single fp16 H plane (reuse X) ----
        {
            const float* b1s = (const float*)(smem + OFF_B1);
            #pragma unroll
            for (int mt = 0; mt < 4; ++mt)
                #pragma unroll
                for (int nt = 0; nt < 4; ++nt) {
                    int row = wm * 64 + mt * 16 + (lid >> 2);
                    int col = wn * 32 + nt * 8 + (lid & 3) * 2;
                    float bc0 = b1s[col], bc1 = b1s[col + 1];
                    float h0 = fmaxf(acc[mt][nt][0] + bc0, 0.f);
                    float h1 = fmaxf(acc[mt][nt][1] + bc1, 0.f);
                    float h2 = fmaxf(acc[mt][nt][2] + bc0, 0.f);
                    float h3 = fmaxf(acc[mt][nt][3] + bc1, 0.f);
                    uint32_t oA = sw128((uint32_t)(row * 128 + col * 2));
                    uint32_t oB = sw128((uint32_t)((row + 8) * 128 + col * 2));
                    *(uint32_t*)(smem + OFF_X + oA) = f2h2(h0, h1);
                    *(uint32_t*)(smem + OFF_X + oB) = f2h2(h2, h3);
                    acc[mt][nt][0] = acc[mt][nt][1] = acc[mt][nt][2] = acc[mt][nt][3] = 0.f;
                }
        }
        __syncthreads();

        // ================= GEMM2 (K = 64) =================
        #pragma unroll
        for (int ks = 0; ks < 4; ++ks) kstep(ks * 16, sb + OFF_W2, ks * 16);

        // ---- epilogue: + bias2, float2 stores; reset acc for next tile ----
        {
            const float* b2s = (const float*)(smem + OFF_B2);
            #pragma unroll
            for (int mt = 0; mt < 4; ++mt)
                #pragma unroll
                for (int nt = 0; nt < 4; ++nt) {
                    int row = wm * 64 + mt * 16 + (lid >> 2);
                    int col = wn * 32 + nt * 8 + (lid & 3) * 2;
                    float bc0 = b2s[col], bc1 = b2s[col + 1];
                    int eA = e0 + row, eB = e0 + row + 8;
                    if (eA < E)
                        *(float2*)&out[(size_t)eA * 64 + col] =
                            make_float2(acc[mt][nt][0] + bc0, acc[mt][nt][1] + bc1);
                    if (eB < E)
                        *(float2*)&out[(size_t)eB * 64 + col] =
                            make_float2(acc[mt][nt][2] + bc0, acc[mt][nt][3] + bc1);
                    acc[mt][nt][0] = acc[mt][nt][1] = acc[mt][nt][2] = acc[mt][nt][3] = 0.f;
                }
        }
        __syncthreads();                           // H reads done before next stage_x
    }
}

extern "C" void kernel_launch(void* const* d_in, const int* in_sizes, int n_in,
                              void* d_out, int out_size)
{
    const float* src = (const float*)d_in[0];
    const float* dst = (const float*)d_in[1];
    const float* ea  = (const float*)d_in[2];
    const float* W1  = (const float*)d_in[5];
    const float* b1  = (const float*)d_in[6];
    const float* W2  = (const float*)d_in[7];
    const float* b2  = (const float*)d_in[8];
    float* out = (float*)d_out;

    int E = in_sizes[0] / 64;
    int ntiles = (E + M_TILE - 1) / M_TILE;

    cudaFuncSetAttribute(edge_mlp_f16,
                         cudaFuncAttributeMaxDynamicSharedMemorySize, SMEM_BYTES);

    int grid = 2 * 148;
    if (grid > ntiles) grid = ntiles;
    edge_mlp_f16<<<grid, THREADS, SMEM_BYTES>>>(src, dst, ea, W1, b1, W2, b2, out, E, ntiles);
}